// round 4
// baseline (speedup 1.0000x reference)
#include <cuda_runtime.h>
#include <cuda_bf16.h>
#include <cstdint>

#define T_DIM 256
#define B_DIM 256
#define H_DIM 512
#define K_DIM 64
#define M_DIM (T_DIM * B_DIM)

// Scratch (device globals; no allocations anywhere)
__device__ float g_em[(size_t)M_DIM * K_DIM];   // emissions [T,B,K] f32
__device__ float g_diff[B_DIM];                 // per-batch forward - gold

__device__ __forceinline__ uint32_t f2bf2(float lo, float hi) {
    uint32_t r;
    asm("cvt.rn.bf16x2.f32 %0, %1, %2;" : "=r"(r) : "f"(hi), "f"(lo));
    return r;
}

// ---------------------------------------------------------------------------
// Kernel 1: emissions GEMM  em[m,k] = sum_h hid[m,h] * W[k,h] + b[k]
// Warp computes 32 rows x 64 cols (two m16 tiles share each B fragment).
// B staged in SMEM as u64=(bf16x2 lo,hi) pairs; per k-iter 4 LDS.128 per
// thread, bank-exact swizzle: u64 idx = (kk*4+tg)*64 + (p*8+(g^(tg<<1)))*2+half
// Grid = 256 blocks -> single wave at 2 blocks/SM.
// ---------------------------------------------------------------------------
extern __shared__ unsigned long long sB[];   // 8192 u64 = 64 KB dynamic

__global__ __launch_bounds__(256, 2) void emis_gemm(const float* __restrict__ hid,
                                                    const float* __restrict__ W,
                                                    const float* __restrict__ bias) {
    int tid = threadIdx.x;

    // Stage W. i enumerates (n, kk, tg); u64 = (W2[n][8kk+tg], W2[n][8kk+tg+4]).
    for (int i = tid; i < (K_DIM * H_DIM) / 4; i += 256) {
        int n  = i >> 7;
        int r  = i & 127;
        int kk = r >> 2;
        int tg = r & 3;
        const float2* src = (const float2*)(W + n * H_DIM + kk * 16 + tg * 2);
        float2 lo = src[0];
        float2 hi = src[4];
        uint32_t wl = f2bf2(lo.x, lo.y);
        uint32_t wh = f2bf2(hi.x, hi.y);
        unsigned long long u;
        asm("mov.b64 %0, {%1,%2};" : "=l"(u) : "r"(wl), "r"(wh));
        int g = n & 7, nt = n >> 3;
        int p = nt >> 1, half = nt & 1;
        sB[(kk * 4 + tg) * 64 + (p * 8 + (g ^ (tg << 1))) * 2 + half] = u;
    }
    __syncthreads();

    int warp = tid >> 5;
    int lane = tid & 31;
    int g  = lane >> 2;   // 0..7
    int tg = lane & 3;    // 0..3
    int row0 = blockIdx.x * 256 + warp * 32;

    const float* a0p = hid + (size_t)(row0 + g)      * H_DIM + tg * 2;
    const float* a1p = hid + (size_t)(row0 + g + 8)  * H_DIM + tg * 2;
    const float* a2p = hid + (size_t)(row0 + g + 16) * H_DIM + tg * 2;
    const float* a3p = hid + (size_t)(row0 + g + 24) * H_DIM + tg * 2;

    float acc[16][4];
#pragma unroll
    for (int nt = 0; nt < 16; nt++)
#pragma unroll
        for (int q = 0; q < 4; q++) acc[nt][q] = 0.f;

    // prime A double-buffer (2 tiles x 4 fragments)
    float2 v0 = *(const float2*)(a0p),     v1 = *(const float2*)(a1p);
    float2 v2 = *(const float2*)(a0p + 8), v3 = *(const float2*)(a1p + 8);
    float2 w0 = *(const float2*)(a2p),     w1 = *(const float2*)(a3p);
    float2 w2 = *(const float2*)(a2p + 8), w3 = *(const float2*)(a3p + 8);

#pragma unroll 4
    for (int kk = 0; kk < 32; kk++) {
        uint32_t a0 = f2bf2(v0.x, v0.y), a1 = f2bf2(v1.x, v1.y);
        uint32_t a2 = f2bf2(v2.x, v2.y), a3 = f2bf2(v3.x, v3.y);
        uint32_t c0 = f2bf2(w0.x, w0.y), c1 = f2bf2(w1.x, w1.y);
        uint32_t c2 = f2bf2(w2.x, w2.y), c3 = f2bf2(w3.x, w3.y);
        if (kk < 31) {
            int k0 = (kk + 1) * 16;
            v0 = *(const float2*)(a0p + k0);     v1 = *(const float2*)(a1p + k0);
            v2 = *(const float2*)(a0p + k0 + 8); v3 = *(const float2*)(a1p + k0 + 8);
            w0 = *(const float2*)(a2p + k0);     w1 = *(const float2*)(a3p + k0);
            w2 = *(const float2*)(a2p + k0 + 8); w3 = *(const float2*)(a3p + k0 + 8);
        }
        const unsigned long long* rowp = sB + ((kk * 4 + tg) << 6) + (g ^ (tg << 1)) * 2;
#pragma unroll
        for (int p = 0; p < 4; p++) {
            uint4 bb = *(const uint4*)(rowp + p * 16);
            int n0 = 2 * p, n1 = 2 * p + 1;
            asm volatile(
                "mma.sync.aligned.m16n8k16.row.col.f32.bf16.bf16.f32 "
                "{%0,%1,%2,%3}, {%4,%5,%6,%7}, {%8,%9}, {%0,%1,%2,%3};"
                : "+f"(acc[n0][0]), "+f"(acc[n0][1]), "+f"(acc[n0][2]), "+f"(acc[n0][3])
                : "r"(a0), "r"(a1), "r"(a2), "r"(a3), "r"(bb.x), "r"(bb.y));
            asm volatile(
                "mma.sync.aligned.m16n8k16.row.col.f32.bf16.bf16.f32 "
                "{%0,%1,%2,%3}, {%4,%5,%6,%7}, {%8,%9}, {%0,%1,%2,%3};"
                : "+f"(acc[n1][0]), "+f"(acc[n1][1]), "+f"(acc[n1][2]), "+f"(acc[n1][3])
                : "r"(a0), "r"(a1), "r"(a2), "r"(a3), "r"(bb.z), "r"(bb.w));
            asm volatile(
                "mma.sync.aligned.m16n8k16.row.col.f32.bf16.bf16.f32 "
                "{%0,%1,%2,%3}, {%4,%5,%6,%7}, {%8,%9}, {%0,%1,%2,%3};"
                : "+f"(acc[n0 + 8][0]), "+f"(acc[n0 + 8][1]), "+f"(acc[n0 + 8][2]), "+f"(acc[n0 + 8][3])
                : "r"(c0), "r"(c1), "r"(c2), "r"(c3), "r"(bb.x), "r"(bb.y));
            asm volatile(
                "mma.sync.aligned.m16n8k16.row.col.f32.bf16.bf16.f32 "
                "{%0,%1,%2,%3}, {%4,%5,%6,%7}, {%8,%9}, {%0,%1,%2,%3};"
                : "+f"(acc[n1 + 8][0]), "+f"(acc[n1 + 8][1]), "+f"(acc[n1 + 8][2]), "+f"(acc[n1 + 8][3])
                : "r"(c0), "r"(c1), "r"(c2), "r"(c3), "r"(bb.z), "r"(bb.w));
        }
    }

    int r0 = row0 + g;
#pragma unroll
    for (int nt = 0; nt < 8; nt++) {
        int c = nt * 8 + tg * 2;
        float b0v = bias[c], b1v = bias[c + 1];
        float2 o;
        o.x = acc[nt][0] + b0v; o.y = acc[nt][1] + b1v;
        *(float2*)(g_em + (size_t)r0 * K_DIM + c) = o;
        o.x = acc[nt][2] + b0v; o.y = acc[nt][3] + b1v;
        *(float2*)(g_em + (size_t)(r0 + 8) * K_DIM + c) = o;
        o.x = acc[nt + 8][0] + b0v; o.y = acc[nt + 8][1] + b1v;
        *(float2*)(g_em + (size_t)(r0 + 16) * K_DIM + c) = o;
        o.x = acc[nt + 8][2] + b0v; o.y = acc[nt + 8][3] + b1v;
        *(float2*)(g_em + (size_t)(r0 + 24) * K_DIM + c) = o;
    }
}

// ---------------------------------------------------------------------------
// Kernel 2: CRF DP + gold. ONE block (64 thr, 2 warps) per batch -> per-step
// sync is a cheap block-wide BAR.SYNC. Log-free recurrence; em exp pipeline
// is 2 iterations deep so LDG latency never binds.
// ---------------------------------------------------------------------------
#define FMA2(acc, a, b) \
    asm("fma.rn.f32x2 %0, %1, %2, %3;" : "=l"(acc) : "l"(a), "l"(b), "l"(acc))

__global__ __launch_bounds__(64) void crf_dp(const int* __restrict__ lens,
                                             const int* __restrict__ tags,
                                             const float* __restrict__ trans,
                                             const float* __restrict__ begin,
                                             const float* __restrict__ endt) {
    int j    = threadIdx.x;       // 0..63
    int lane = j & 31;
    int wing = j >> 5;
    int b    = blockIdx.x;
    int len  = lens[b];

    __shared__ __align__(16) float sm_u[2][64];
    __shared__ float sm_inv[2];
    __shared__ float sm_g[2];

    // ---- gold path score ----
    float gpart = 0.f;
    for (int t = j; t < len; t += 64) {
        int tag = tags[t * B_DIM + b];
        float inc;
        if (t == 0) inc = begin[tag];
        else        inc = trans[tag * K_DIM + tags[(t - 1) * B_DIM + b]];
        inc += g_em[((size_t)t * B_DIM + b) * K_DIM + tag];
        gpart += inc;
    }
#pragma unroll
    for (int o = 16; o; o >>= 1) gpart += __shfl_down_sync(0xffffffffu, gpart, o);
    if (lane == 0) sm_g[wing] = gpart;
    __syncthreads();
    float goldv = 0.f;
    if (j == 0)
        goldv = sm_g[0] + sm_g[1] + endt[tags[(len - 1) * B_DIM + b]];

    // ---- exp(transition) row j, packed f32x2 ----
    unsigned long long eT2[32];
    {
        const float4* tr4 = (const float4*)(trans + j * K_DIM);
#pragma unroll
        for (int q = 0; q < 16; q++) {
            float4 v = tr4[q];
            float e0 = __expf(v.x), e1 = __expf(v.y);
            float e2 = __expf(v.z), e3 = __expf(v.w);
            asm("mov.b64 %0, {%1,%2};" : "=l"(eT2[2*q])   : "f"(e0), "f"(e1));
            asm("mov.b64 %0, {%1,%2};" : "=l"(eT2[2*q+1]) : "f"(e2), "f"(e3));
        }
    }

    // ---- init (t=0): u0_j = exp(alpha_j(0) - alpha_0(0)), C = alpha_0(0) ----
    float a00 = begin[0] + g_em[(size_t)b * K_DIM];
    float u0  = __expf(begin[j] + g_em[(size_t)b * K_DIM + j] - a00);
    float C = a00;                      // thread 0 only
    sm_u[0][j] = u0;
    if (j == 0) sm_inv[0] = 1.f;
    float u_reg = u0;

    // em pipeline (index clamped; garbage values are never consumed):
    //   x_cur/em0_cur : em[t+1]   x_n1/em0_n1 : em[t+2]
    //   emB : em[t+3] raw         emA : em[t+4] in flight
    float x_cur, em0_cur, x_n1, em0_n1, emBj, emB0, emAj, emA0;
    {
        int i1 = 1 < len ? 1 : len - 1;
        int i2 = 2 < len ? 2 : len - 1;
        int i3 = 3 < len ? 3 : len - 1;
        int i4 = 4 < len ? 4 : len - 1;
        size_t b1 = ((size_t)i1 * B_DIM + b) * K_DIM;
        size_t b2 = ((size_t)i2 * B_DIM + b) * K_DIM;
        size_t b3 = ((size_t)i3 * B_DIM + b) * K_DIM;
        size_t b4 = ((size_t)i4 * B_DIM + b) * K_DIM;
        float e1j = g_em[b1 + j], e10 = g_em[b1];
        float e2j = g_em[b2 + j], e20 = g_em[b2];
        x_cur = __expf(e1j - e10); em0_cur = e10;
        x_n1  = __expf(e2j - e20); em0_n1  = e20;
        emBj = g_em[b3 + j]; emB0 = g_em[b3];
        emAj = g_em[b4 + j]; emA0 = g_em[b4];
    }
    __syncthreads();

    // ---- serial DP: len-1 steps, one block-wide bar each ----
    for (int t = 0; t < len - 1; t++) {
        int buf = t & 1, nbuf = buf ^ 1;

        float inv = sm_inv[buf];
        const ulonglong2* pp = (const ulonglong2*)sm_u[buf];
        unsigned long long acc0 = 0, acc1 = 0, acc2 = 0, acc3 = 0;
#pragma unroll
        for (int q = 0; q < 16; q += 2) {
            ulonglong2 va = pp[q];
            ulonglong2 vb = pp[q + 1];
            FMA2(acc0, va.x, eT2[2*q]);
            FMA2(acc1, va.y, eT2[2*q+1]);
            FMA2(acc2, vb.x, eT2[2*q+2]);
            FMA2(acc3, vb.y, eT2[2*q+3]);
        }
        float s;
        {
            float l0, h0, l1, h1, l2, h2, l3, h3;
            asm("mov.b64 {%0,%1}, %2;" : "=f"(l0), "=f"(h0) : "l"(acc0));
            asm("mov.b64 {%0,%1}, %2;" : "=f"(l1), "=f"(h1) : "l"(acc1));
            asm("mov.b64 {%0,%1}, %2;" : "=f"(l2), "=f"(h2) : "l"(acc2));
            asm("mov.b64 {%0,%1}, %2;" : "=f"(l3), "=f"(h3) : "l"(acc3));
            s = ((l0 + h0) + (l1 + h1)) + ((l2 + h2) + (l3 + h3));
        }
        float un = s * (x_cur * inv);
        sm_u[nbuf][j] = un;
        if (j == 0) {
            float invn;
            asm("rcp.approx.f32 %0, %1;" : "=f"(invn) : "f"(s));
            sm_inv[nbuf] = invn;
            C += em0_cur - __logf(inv);   // uses the ACTUAL inv applied to u
        }
        u_reg = un;

        // rotate em pipeline (off critical path; 2-iter load->use distance)
        x_cur = x_n1; em0_cur = em0_n1;
        x_n1 = __expf(emBj - emB0); em0_n1 = emB0;
        emBj = emAj; emB0 = emA0;
        int tl = (t + 5 < len) ? t + 5 : len - 1;
        size_t base = ((size_t)tl * B_DIM + b) * K_DIM;
        emAj = g_em[base + j]; emA0 = g_em[base];

        __syncthreads();
    }

    // ---- forward = C + log(sum_j u_j * exp(end_j)) ----
    float val = u_reg * __expf(endt[j]);
#pragma unroll
    for (int o = 16; o; o >>= 1) val += __shfl_down_sync(0xffffffffu, val, o);
    if (lane == 0) sm_g[wing] = val;
    __syncthreads();
    if (j == 0) {
        float fwd = C + __logf(sm_g[0] + sm_g[1]);
        g_diff[b] = fwd - goldv;
    }
}

// ---------------------------------------------------------------------------
// Kernel 3: deterministic final reduction
// ---------------------------------------------------------------------------
__global__ void final_reduce(float* __restrict__ out) {
    __shared__ float s[256];
    int t = threadIdx.x;
    s[t] = g_diff[t];
    __syncthreads();
    for (int k = 128; k > 0; k >>= 1) {
        if (t < k) s[t] += s[t + k];
        __syncthreads();
    }
    if (t == 0) out[0] = s[0];
}

// ---------------------------------------------------------------------------
extern "C" void kernel_launch(void* const* d_in, const int* in_sizes, int n_in,
                              void* d_out, int out_size) {
    const float* hiddens = (const float*)d_in[0];   // [T,B,H] f32
    const int*   lens    = (const int*)d_in[1];     // [B]
    const int*   tags    = (const int*)d_in[2];     // [T,B]
    const float* W       = (const float*)d_in[3];   // [K,H]
    const float* bias    = (const float*)d_in[4];   // [K]
    const float* begin   = (const float*)d_in[5];   // [K]
    const float* trans   = (const float*)d_in[6];   // [K,K]
    const float* endt    = (const float*)d_in[7];   // [K]
    float* out = (float*)d_out;

    cudaFuncSetAttribute(emis_gemm, cudaFuncAttributeMaxDynamicSharedMemorySize, 65536);

    emis_gemm<<<M_DIM / 256, 256, 65536>>>(hiddens, W, bias);
    crf_dp<<<B_DIM, 64>>>(lens, tags, trans, begin, endt);
    final_reduce<<<1, 256>>>(out);
}

// round 5
// speedup vs baseline: 1.0212x; 1.0212x over previous
#include <cuda_runtime.h>
#include <cuda_bf16.h>
#include <cstdint>

#define T_DIM 256
#define B_DIM 256
#define H_DIM 512
#define K_DIM 64
#define M_DIM (T_DIM * B_DIM)

// Scratch (device globals; no allocations anywhere)
__device__ float g_em[(size_t)M_DIM * K_DIM];   // emissions [T,B,K] f32
__device__ float g_diff[B_DIM];                 // per-batch forward - gold

__device__ __forceinline__ uint32_t f2bf2(float lo, float hi) {
    uint32_t r;
    asm("cvt.rn.bf16x2.f32 %0, %1, %2;" : "=r"(r) : "f"(hi), "f"(lo));
    return r;
}

// ---------------------------------------------------------------------------
// Kernel 1: emissions GEMM  (unchanged from R4: 54.3us measured)
// Warp computes 32 rows x 64 cols; B staged in SMEM, 4 LDS.128/thread/k-iter.
// ---------------------------------------------------------------------------
extern __shared__ unsigned long long sB[];   // 8192 u64 = 64 KB dynamic

__global__ __launch_bounds__(256, 2) void emis_gemm(const float* __restrict__ hid,
                                                    const float* __restrict__ W,
                                                    const float* __restrict__ bias) {
    int tid = threadIdx.x;

    for (int i = tid; i < (K_DIM * H_DIM) / 4; i += 256) {
        int n  = i >> 7;
        int r  = i & 127;
        int kk = r >> 2;
        int tg = r & 3;
        const float2* src = (const float2*)(W + n * H_DIM + kk * 16 + tg * 2);
        float2 lo = src[0];
        float2 hi = src[4];
        uint32_t wl = f2bf2(lo.x, lo.y);
        uint32_t wh = f2bf2(hi.x, hi.y);
        unsigned long long u;
        asm("mov.b64 %0, {%1,%2};" : "=l"(u) : "r"(wl), "r"(wh));
        int g = n & 7, nt = n >> 3;
        int p = nt >> 1, half = nt & 1;
        sB[(kk * 4 + tg) * 64 + (p * 8 + (g ^ (tg << 1))) * 2 + half] = u;
    }
    __syncthreads();

    int warp = tid >> 5;
    int lane = tid & 31;
    int g  = lane >> 2;
    int tg = lane & 3;
    int row0 = blockIdx.x * 256 + warp * 32;

    const float* a0p = hid + (size_t)(row0 + g)      * H_DIM + tg * 2;
    const float* a1p = hid + (size_t)(row0 + g + 8)  * H_DIM + tg * 2;
    const float* a2p = hid + (size_t)(row0 + g + 16) * H_DIM + tg * 2;
    const float* a3p = hid + (size_t)(row0 + g + 24) * H_DIM + tg * 2;

    float acc[16][4];
#pragma unroll
    for (int nt = 0; nt < 16; nt++)
#pragma unroll
        for (int q = 0; q < 4; q++) acc[nt][q] = 0.f;

    float2 v0 = *(const float2*)(a0p),     v1 = *(const float2*)(a1p);
    float2 v2 = *(const float2*)(a0p + 8), v3 = *(const float2*)(a1p + 8);
    float2 w0 = *(const float2*)(a2p),     w1 = *(const float2*)(a3p);
    float2 w2 = *(const float2*)(a2p + 8), w3 = *(const float2*)(a3p + 8);

#pragma unroll 4
    for (int kk = 0; kk < 32; kk++) {
        uint32_t a0 = f2bf2(v0.x, v0.y), a1 = f2bf2(v1.x, v1.y);
        uint32_t a2 = f2bf2(v2.x, v2.y), a3 = f2bf2(v3.x, v3.y);
        uint32_t c0 = f2bf2(w0.x, w0.y), c1 = f2bf2(w1.x, w1.y);
        uint32_t c2 = f2bf2(w2.x, w2.y), c3 = f2bf2(w3.x, w3.y);
        if (kk < 31) {
            int k0 = (kk + 1) * 16;
            v0 = *(const float2*)(a0p + k0);     v1 = *(const float2*)(a1p + k0);
            v2 = *(const float2*)(a0p + k0 + 8); v3 = *(const float2*)(a1p + k0 + 8);
            w0 = *(const float2*)(a2p + k0);     w1 = *(const float2*)(a3p + k0);
            w2 = *(const float2*)(a2p + k0 + 8); w3 = *(const float2*)(a3p + k0 + 8);
        }
        const unsigned long long* rowp = sB + ((kk * 4 + tg) << 6) + (g ^ (tg << 1)) * 2;
#pragma unroll
        for (int p = 0; p < 4; p++) {
            uint4 bb = *(const uint4*)(rowp + p * 16);
            int n0 = 2 * p, n1 = 2 * p + 1;
            asm volatile(
                "mma.sync.aligned.m16n8k16.row.col.f32.bf16.bf16.f32 "
                "{%0,%1,%2,%3}, {%4,%5,%6,%7}, {%8,%9}, {%0,%1,%2,%3};"
                : "+f"(acc[n0][0]), "+f"(acc[n0][1]), "+f"(acc[n0][2]), "+f"(acc[n0][3])
                : "r"(a0), "r"(a1), "r"(a2), "r"(a3), "r"(bb.x), "r"(bb.y));
            asm volatile(
                "mma.sync.aligned.m16n8k16.row.col.f32.bf16.bf16.f32 "
                "{%0,%1,%2,%3}, {%4,%5,%6,%7}, {%8,%9}, {%0,%1,%2,%3};"
                : "+f"(acc[n1][0]), "+f"(acc[n1][1]), "+f"(acc[n1][2]), "+f"(acc[n1][3])
                : "r"(a0), "r"(a1), "r"(a2), "r"(a3), "r"(bb.z), "r"(bb.w));
            asm volatile(
                "mma.sync.aligned.m16n8k16.row.col.f32.bf16.bf16.f32 "
                "{%0,%1,%2,%3}, {%4,%5,%6,%7}, {%8,%9}, {%0,%1,%2,%3};"
                : "+f"(acc[n0 + 8][0]), "+f"(acc[n0 + 8][1]), "+f"(acc[n0 + 8][2]), "+f"(acc[n0 + 8][3])
                : "r"(c0), "r"(c1), "r"(c2), "r"(c3), "r"(bb.x), "r"(bb.y));
            asm volatile(
                "mma.sync.aligned.m16n8k16.row.col.f32.bf16.bf16.f32 "
                "{%0,%1,%2,%3}, {%4,%5,%6,%7}, {%8,%9}, {%0,%1,%2,%3};"
                : "+f"(acc[n1 + 8][0]), "+f"(acc[n1 + 8][1]), "+f"(acc[n1 + 8][2]), "+f"(acc[n1 + 8][3])
                : "r"(c0), "r"(c1), "r"(c2), "r"(c3), "r"(bb.z), "r"(bb.w));
        }
    }

    int r0 = row0 + g;
#pragma unroll
    for (int nt = 0; nt < 8; nt++) {
        int c = nt * 8 + tg * 2;
        float b0v = bias[c], b1v = bias[c + 1];
        float2 o;
        o.x = acc[nt][0] + b0v; o.y = acc[nt][1] + b1v;
        *(float2*)(g_em + (size_t)r0 * K_DIM + c) = o;
        o.x = acc[nt][2] + b0v; o.y = acc[nt][3] + b1v;
        *(float2*)(g_em + (size_t)(r0 + 8) * K_DIM + c) = o;
        o.x = acc[nt + 8][0] + b0v; o.y = acc[nt + 8][1] + b1v;
        *(float2*)(g_em + (size_t)(r0 + 16) * K_DIM + c) = o;
        o.x = acc[nt + 8][2] + b0v; o.y = acc[nt + 8][3] + b1v;
        *(float2*)(g_em + (size_t)(r0 + 24) * K_DIM + c) = o;
    }
}

// ---------------------------------------------------------------------------
// Kernel 2: CRF DP + gold. ONE WARP per batch: no barriers, no cross-warp
// dependencies. Lane l owns rows j0=l, j1=l+32; exp(trans) rows live in 128
// registers packed f32x2 as (i, i+32) pairs matching the u float2 layout.
// Per step: STS.64 + syncwarp + 16 broadcast LDS.128 + 64 FMA2.
// Delayed-inv normalization: rcp/shfl/log are consumed next step.
// ---------------------------------------------------------------------------
#define FMA2(acc, a, b) \
    asm("fma.rn.f32x2 %0, %1, %2, %3;" : "=l"(acc) : "l"(a), "l"(b), "l"(acc))

__global__ __launch_bounds__(32) void crf_dp(const int* __restrict__ lens,
                                             const int* __restrict__ tags,
                                             const float* __restrict__ trans,
                                             const float* __restrict__ begin,
                                             const float* __restrict__ endt) {
    int lane = threadIdx.x;       // 0..31
    int b    = blockIdx.x;
    int j0   = lane, j1 = lane + 32;
    int len  = lens[b];

    __shared__ __align__(16) float2 sm_u[2][32];

    // ---- gold path score (strided over t, warp reduce) ----
    float gpart = 0.f;
    for (int t = lane; t < len; t += 32) {
        int tag = tags[t * B_DIM + b];
        float inc;
        if (t == 0) inc = begin[tag];
        else        inc = trans[tag * K_DIM + tags[(t - 1) * B_DIM + b]];
        inc += g_em[((size_t)t * B_DIM + b) * K_DIM + tag];
        gpart += inc;
    }
#pragma unroll
    for (int o = 16; o; o >>= 1) gpart += __shfl_down_sync(0xffffffffu, gpart, o);
    float goldv = gpart;          // valid on lane 0 only
    if (lane == 0) goldv += endt[tags[(len - 1) * B_DIM + b]];

    // ---- exp(trans) rows j0, j1 packed f32x2 as (i, i+32) pairs ----
    unsigned long long eTlo[32], eThi[32];
    {
        const float4* t0 = (const float4*)(trans + j0 * K_DIM);
        const float4* t1 = (const float4*)(trans + j1 * K_DIM);
#pragma unroll
        for (int q = 0; q < 8; q++) {
            float4 aL = t0[q], aH = t0[q + 8];     // cols 4q..4q+3 and +32
            float4 bL = t1[q], bH = t1[q + 8];
#pragma unroll
            for (int r = 0; r < 4; r++) {
                float a0 = __expf(r == 0 ? aL.x : r == 1 ? aL.y : r == 2 ? aL.z : aL.w);
                float a1 = __expf(r == 0 ? aH.x : r == 1 ? aH.y : r == 2 ? aH.z : aH.w);
                float b0 = __expf(r == 0 ? bL.x : r == 1 ? bL.y : r == 2 ? bL.z : bL.w);
                float b1 = __expf(r == 0 ? bH.x : r == 1 ? bH.y : r == 2 ? bH.z : bH.w);
                asm("mov.b64 %0, {%1,%2};" : "=l"(eTlo[4*q + r]) : "f"(a0), "f"(a1));
                asm("mov.b64 %0, {%1,%2};" : "=l"(eThi[4*q + r]) : "f"(b0), "f"(b1));
            }
        }
    }

    // ---- init: u = exp(alpha(0) - a00), C = a00, invA = 1 ----
    float em00 = g_em[(size_t)b * K_DIM];             // broadcast load
    float a00  = begin[0] + em00;
    float2 u2;
    u2.x = __expf(begin[j0] + g_em[(size_t)b * K_DIM + j0] - a00);
    u2.y = __expf(begin[j1] + g_em[(size_t)b * K_DIM + j1] - a00);
    float C = a00;
    float invA = 1.f, linvA = 0.f;    // rcp applied this step, and its exact log

    // ---- em pipeline: x_cur = exp(em[t+1][j]-em[t+1][0]) ; raw stages ahead ----
    float2 x_cur, x_n1;
    float em0_cur, em0_n1;
    float emB_l, emB_h, emA_l, emA_h;   // raw em[t+3], em[t+4]
    {
        int i1 = 1 < len ? 1 : len - 1;
        int i2 = 2 < len ? 2 : len - 1;
        int i3 = 3 < len ? 3 : len - 1;
        int i4 = 4 < len ? 4 : len - 1;
        size_t b1 = ((size_t)i1 * B_DIM + b) * K_DIM;
        size_t b2 = ((size_t)i2 * B_DIM + b) * K_DIM;
        size_t b3 = ((size_t)i3 * B_DIM + b) * K_DIM;
        size_t b4 = ((size_t)i4 * B_DIM + b) * K_DIM;
        float e1l = g_em[b1 + j0], e1h = g_em[b1 + j1];
        float e2l = g_em[b2 + j0], e2h = g_em[b2 + j1];
        float e10 = __shfl_sync(0xffffffffu, e1l, 0);
        float e20 = __shfl_sync(0xffffffffu, e2l, 0);
        x_cur.x = __expf(e1l - e10); x_cur.y = __expf(e1h - e10); em0_cur = e10;
        x_n1.x  = __expf(e2l - e20); x_n1.y  = __expf(e2h - e20); em0_n1  = e20;
        emB_l = g_em[b3 + j0]; emB_h = g_em[b3 + j1];
        emA_l = g_em[b4 + j0]; emA_h = g_em[b4 + j1];
    }

    // ---- serial DP: len-1 steps, warp-local only ----
    for (int t = 0; t < len - 1; t++) {
        int buf = t & 1;
        sm_u[buf][lane] = u2;
        __syncwarp();

        const ulonglong2* pp = (const ulonglong2*)sm_u[buf];
        unsigned long long al0 = 0, al1 = 0, ah0 = 0, ah1 = 0;
#pragma unroll
        for (int q = 0; q < 16; q++) {
            ulonglong2 v = pp[q];
            FMA2(al0, v.x, eTlo[2*q]);
            FMA2(al1, v.y, eTlo[2*q+1]);
            FMA2(ah0, v.x, eThi[2*q]);
            FMA2(ah1, v.y, eThi[2*q+1]);
        }
        float s_lo, s_hi;
        {
            float p0, p1, p2, p3, p4, p5, p6, p7;
            asm("mov.b64 {%0,%1}, %2;" : "=f"(p0), "=f"(p1) : "l"(al0));
            asm("mov.b64 {%0,%1}, %2;" : "=f"(p2), "=f"(p3) : "l"(al1));
            asm("mov.b64 {%0,%1}, %2;" : "=f"(p4), "=f"(p5) : "l"(ah0));
            asm("mov.b64 {%0,%1}, %2;" : "=f"(p6), "=f"(p7) : "l"(ah1));
            s_lo = (p0 + p1) + (p2 + p3);
            s_hi = (p4 + p5) + (p6 + p7);
        }
        // u' = s * x * invA  (invA from PREVIOUS step's s0; exact via linvA)
        u2.x = s_lo * x_cur.x * invA;
        u2.y = s_hi * x_cur.y * invA;
        C += em0_cur - linvA;

        // next-step normalizer (off critical path)
        float s0 = __shfl_sync(0xffffffffu, s_lo, 0);
        asm("rcp.approx.f32 %0, %1;" : "=f"(invA) : "f"(s0));
        linvA = __logf(invA);

        // rotate em pipeline (2-deep)
        x_cur = x_n1; em0_cur = em0_n1;
        float eb0 = __shfl_sync(0xffffffffu, emB_l, 0);
        x_n1.x = __expf(emB_l - eb0); x_n1.y = __expf(emB_h - eb0); em0_n1 = eb0;
        emB_l = emA_l; emB_h = emA_h;
        int tl = (t + 5 < len) ? t + 5 : len - 1;
        size_t base = ((size_t)tl * B_DIM + b) * K_DIM;
        emA_l = g_em[base + j0]; emA_h = g_em[base + j1];
    }

    // ---- forward = C + log(sum_j u_j * exp(end_j)) ----
    float val = u2.x * __expf(endt[j0]) + u2.y * __expf(endt[j1]);
#pragma unroll
    for (int o = 16; o; o >>= 1) val += __shfl_down_sync(0xffffffffu, val, o);
    if (lane == 0)
        g_diff[b] = C + __logf(val) - goldv;
}

// ---------------------------------------------------------------------------
// Kernel 3: deterministic final reduction
// ---------------------------------------------------------------------------
__global__ void final_reduce(float* __restrict__ out) {
    __shared__ float s[256];
    int t = threadIdx.x;
    s[t] = g_diff[t];
    __syncthreads();
    for (int k = 128; k > 0; k >>= 1) {
        if (t < k) s[t] += s[t + k];
        __syncthreads();
    }
    if (t == 0) out[0] = s[0];
}

// ---------------------------------------------------------------------------
extern "C" void kernel_launch(void* const* d_in, const int* in_sizes, int n_in,
                              void* d_out, int out_size) {
    const float* hiddens = (const float*)d_in[0];   // [T,B,H] f32
    const int*   lens    = (const int*)d_in[1];     // [B]
    const int*   tags    = (const int*)d_in[2];     // [T,B]
    const float* W       = (const float*)d_in[3];   // [K,H]
    const float* bias    = (const float*)d_in[4];   // [K]
    const float* begin   = (const float*)d_in[5];   // [K]
    const float* trans   = (const float*)d_in[6];   // [K,K]
    const float* endt    = (const float*)d_in[7];   // [K]
    float* out = (float*)d_out;

    cudaFuncSetAttribute(emis_gemm, cudaFuncAttributeMaxDynamicSharedMemorySize, 65536);

    emis_gemm<<<M_DIM / 256, 256, 65536>>>(hiddens, W, bias);
    crf_dp<<<B_DIM, 32>>>(lens, tags, trans, begin, endt);
    final_reduce<<<1, 256>>>(out);
}

// round 6
// speedup vs baseline: 1.6571x; 1.6227x over previous
#include <cuda_runtime.h>
#include <cuda_bf16.h>
#include <cstdint>

#define T_DIM 256
#define B_DIM 256
#define H_DIM 512
#define K_DIM 64
#define M_DIM (T_DIM * B_DIM)

// Scratch (device globals; no allocations anywhere)
__device__ float g_em[(size_t)M_DIM * K_DIM];   // emissions [T,B,K] f32
__device__ float g_diff[B_DIM];                 // per-batch forward - gold
__device__ unsigned int g_cnt = 0;              // last-block counter (self-resetting)

__device__ __forceinline__ uint32_t f2bf2(float lo, float hi) {
    uint32_t r;
    asm("cvt.rn.bf16x2.f32 %0, %1, %2;" : "=r"(r) : "f"(hi), "f"(lo));
    return r;
}

// ---------------------------------------------------------------------------
// Kernel 1: emissions GEMM  (unchanged; 54.0us measured)
// ---------------------------------------------------------------------------
extern __shared__ unsigned long long sB[];   // 8192 u64 = 64 KB dynamic

__global__ __launch_bounds__(256, 2) void emis_gemm(const float* __restrict__ hid,
                                                    const float* __restrict__ W,
                                                    const float* __restrict__ bias) {
    int tid = threadIdx.x;

    for (int i = tid; i < (K_DIM * H_DIM) / 4; i += 256) {
        int n  = i >> 7;
        int r  = i & 127;
        int kk = r >> 2;
        int tg = r & 3;
        const float2* src = (const float2*)(W + n * H_DIM + kk * 16 + tg * 2);
        float2 lo = src[0];
        float2 hi = src[4];
        uint32_t wl = f2bf2(lo.x, lo.y);
        uint32_t wh = f2bf2(hi.x, hi.y);
        unsigned long long u;
        asm("mov.b64 %0, {%1,%2};" : "=l"(u) : "r"(wl), "r"(wh));
        int g = n & 7, nt = n >> 3;
        int p = nt >> 1, half = nt & 1;
        sB[(kk * 4 + tg) * 64 + (p * 8 + (g ^ (tg << 1))) * 2 + half] = u;
    }
    __syncthreads();

    int warp = tid >> 5;
    int lane = tid & 31;
    int g  = lane >> 2;
    int tg = lane & 3;
    int row0 = blockIdx.x * 256 + warp * 32;

    const float* a0p = hid + (size_t)(row0 + g)      * H_DIM + tg * 2;
    const float* a1p = hid + (size_t)(row0 + g + 8)  * H_DIM + tg * 2;
    const float* a2p = hid + (size_t)(row0 + g + 16) * H_DIM + tg * 2;
    const float* a3p = hid + (size_t)(row0 + g + 24) * H_DIM + tg * 2;

    float acc[16][4];
#pragma unroll
    for (int nt = 0; nt < 16; nt++)
#pragma unroll
        for (int q = 0; q < 4; q++) acc[nt][q] = 0.f;

    float2 v0 = *(const float2*)(a0p),     v1 = *(const float2*)(a1p);
    float2 v2 = *(const float2*)(a0p + 8), v3 = *(const float2*)(a1p + 8);
    float2 w0 = *(const float2*)(a2p),     w1 = *(const float2*)(a3p);
    float2 w2 = *(const float2*)(a2p + 8), w3 = *(const float2*)(a3p + 8);

#pragma unroll 4
    for (int kk = 0; kk < 32; kk++) {
        uint32_t a0 = f2bf2(v0.x, v0.y), a1 = f2bf2(v1.x, v1.y);
        uint32_t a2 = f2bf2(v2.x, v2.y), a3 = f2bf2(v3.x, v3.y);
        uint32_t c0 = f2bf2(w0.x, w0.y), c1 = f2bf2(w1.x, w1.y);
        uint32_t c2 = f2bf2(w2.x, w2.y), c3 = f2bf2(w3.x, w3.y);
        if (kk < 31) {
            int k0 = (kk + 1) * 16;
            v0 = *(const float2*)(a0p + k0);     v1 = *(const float2*)(a1p + k0);
            v2 = *(const float2*)(a0p + k0 + 8); v3 = *(const float2*)(a1p + k0 + 8);
            w0 = *(const float2*)(a2p + k0);     w1 = *(const float2*)(a3p + k0);
            w2 = *(const float2*)(a2p + k0 + 8); w3 = *(const float2*)(a3p + k0 + 8);
        }
        const unsigned long long* rowp = sB + ((kk * 4 + tg) << 6) + (g ^ (tg << 1)) * 2;
#pragma unroll
        for (int p = 0; p < 4; p++) {
            uint4 bb = *(const uint4*)(rowp + p * 16);
            int n0 = 2 * p, n1 = 2 * p + 1;
            asm volatile(
                "mma.sync.aligned.m16n8k16.row.col.f32.bf16.bf16.f32 "
                "{%0,%1,%2,%3}, {%4,%5,%6,%7}, {%8,%9}, {%0,%1,%2,%3};"
                : "+f"(acc[n0][0]), "+f"(acc[n0][1]), "+f"(acc[n0][2]), "+f"(acc[n0][3])
                : "r"(a0), "r"(a1), "r"(a2), "r"(a3), "r"(bb.x), "r"(bb.y));
            asm volatile(
                "mma.sync.aligned.m16n8k16.row.col.f32.bf16.bf16.f32 "
                "{%0,%1,%2,%3}, {%4,%5,%6,%7}, {%8,%9}, {%0,%1,%2,%3};"
                : "+f"(acc[n1][0]), "+f"(acc[n1][1]), "+f"(acc[n1][2]), "+f"(acc[n1][3])
                : "r"(a0), "r"(a1), "r"(a2), "r"(a3), "r"(bb.z), "r"(bb.w));
            asm volatile(
                "mma.sync.aligned.m16n8k16.row.col.f32.bf16.bf16.f32 "
                "{%0,%1,%2,%3}, {%4,%5,%6,%7}, {%8,%9}, {%0,%1,%2,%3};"
                : "+f"(acc[n0 + 8][0]), "+f"(acc[n0 + 8][1]), "+f"(acc[n0 + 8][2]), "+f"(acc[n0 + 8][3])
                : "r"(c0), "r"(c1), "r"(c2), "r"(c3), "r"(bb.x), "r"(bb.y));
            asm volatile(
                "mma.sync.aligned.m16n8k16.row.col.f32.bf16.bf16.f32 "
                "{%0,%1,%2,%3}, {%4,%5,%6,%7}, {%8,%9}, {%0,%1,%2,%3};"
                : "+f"(acc[n1 + 8][0]), "+f"(acc[n1 + 8][1]), "+f"(acc[n1 + 8][2]), "+f"(acc[n1 + 8][3])
                : "r"(c0), "r"(c1), "r"(c2), "r"(c3), "r"(bb.z), "r"(bb.w));
        }
    }

    int r0 = row0 + g;
#pragma unroll
    for (int nt = 0; nt < 8; nt++) {
        int c = nt * 8 + tg * 2;
        float b0v = bias[c], b1v = bias[c + 1];
        float2 o;
        o.x = acc[nt][0] + b0v; o.y = acc[nt][1] + b1v;
        *(float2*)(g_em + (size_t)r0 * K_DIM + c) = o;
        o.x = acc[nt][2] + b0v; o.y = acc[nt][3] + b1v;
        *(float2*)(g_em + (size_t)(r0 + 8) * K_DIM + c) = o;
        o.x = acc[nt + 8][0] + b0v; o.y = acc[nt + 8][1] + b1v;
        *(float2*)(g_em + (size_t)(r0 + 16) * K_DIM + c) = o;
        o.x = acc[nt + 8][2] + b0v; o.y = acc[nt + 8][3] + b1v;
        *(float2*)(g_em + (size_t)(r0 + 24) * K_DIM + c) = o;
    }
}

// ---------------------------------------------------------------------------
// Kernel 2: CRF DP + gold + fused final reduction.
// 2 batches/block (128 thr), 64 threads per batch with named barriers
// (measured-best structure). Thread j holds exp(trans[j][:]) in 32 f32x2
// regs and computes the full 64-dot. Log-free delayed-inv recurrence.
// em pipeline: depth-4 raw LDG ring (load t+7, exp at t+3, use at t+1),
// unroll-4 so ptxas renames ring slots -> no memory stall on critical path.
// ---------------------------------------------------------------------------
#define FMA2(acc, a, b) \
    asm("fma.rn.f32x2 %0, %1, %2, %3;" : "=l"(acc) : "l"(a), "l"(b), "l"(acc))

__global__ __launch_bounds__(128) void crf_dp(const int* __restrict__ lens,
                                              const int* __restrict__ tags,
                                              const float* __restrict__ trans,
                                              const float* __restrict__ begin,
                                              const float* __restrict__ endt,
                                              float* __restrict__ out) {
    int tid  = threadIdx.x;
    int gid  = tid >> 6;
    int j    = tid & 63;
    int lane = tid & 31;
    int wing = (tid >> 5) & 1;
    int b    = blockIdx.x * 2 + gid;
    int len  = lens[b];
    int barid = gid + 1;

    __shared__ __align__(16) float sm_u[2][2][64];
    __shared__ float sm_inv[2][2];
    __shared__ float sm_g[2][2];

#define GBAR() asm volatile("bar.sync %0, 64;" :: "r"(barid) : "memory")

    // ---- gold path score ----
    float gpart = 0.f;
    for (int t = j; t < len; t += 64) {
        int tag = tags[t * B_DIM + b];
        float inc;
        if (t == 0) inc = begin[tag];
        else        inc = trans[tag * K_DIM + tags[(t - 1) * B_DIM + b]];
        inc += g_em[((size_t)t * B_DIM + b) * K_DIM + tag];
        gpart += inc;
    }
#pragma unroll
    for (int o = 16; o; o >>= 1) gpart += __shfl_down_sync(0xffffffffu, gpart, o);
    if (lane == 0) sm_g[gid][wing] = gpart;
    GBAR();
    float goldv = 0.f;
    if (j == 0)
        goldv = sm_g[gid][0] + sm_g[gid][1] + endt[tags[(len - 1) * B_DIM + b]];

    // ---- exp(transition) row j, packed f32x2 ----
    unsigned long long eT2[32];
    {
        const float4* tr4 = (const float4*)(trans + j * K_DIM);
#pragma unroll
        for (int q = 0; q < 16; q++) {
            float4 v = tr4[q];
            float e0 = __expf(v.x), e1 = __expf(v.y);
            float e2 = __expf(v.z), e3 = __expf(v.w);
            asm("mov.b64 %0, {%1,%2};" : "=l"(eT2[2*q])   : "f"(e0), "f"(e1));
            asm("mov.b64 %0, {%1,%2};" : "=l"(eT2[2*q+1]) : "f"(e2), "f"(e3));
        }
    }

    // ---- init (t=0) ----
    float a00 = begin[0] + g_em[(size_t)b * K_DIM];
    float u0  = __expf(begin[j] + g_em[(size_t)b * K_DIM + j] - a00);
    float C = a00;                      // meaningful on j==0 only
    sm_u[gid][0][j] = u0;
    if (j == 0) sm_inv[gid][0] = 1.f;
    float u_reg = u0;

    // ---- em pipeline ----
    // xq[t&1]   : exp(em[t+1][j]-em[t+1][0]) consumed at iter t, refilled for t+3
    // rawJ/raw0[t&3] : raw em[t+3] consumed (exp'd) at iter t, reloaded with t+7
    float xq[2], e0q[2];
    float rawJ[4], raw0[4];
    {
#pragma unroll
        for (int s = 0; s < 4; s++) {
            int idx = (3 + s < len) ? 3 + s : len - 1;
            size_t base = ((size_t)idx * B_DIM + b) * K_DIM;
            rawJ[s] = g_em[base + j];
            raw0[s] = g_em[base];
        }
        int i1 = 1 < len ? 1 : len - 1;
        int i2 = 2 < len ? 2 : len - 1;
        size_t b1 = ((size_t)i1 * B_DIM + b) * K_DIM;
        size_t b2 = ((size_t)i2 * B_DIM + b) * K_DIM;
        float e1j = g_em[b1 + j], e10 = g_em[b1];
        float e2j = g_em[b2 + j], e20 = g_em[b2];
        xq[0] = __expf(e1j - e10); e0q[0] = e10;
        xq[1] = __expf(e2j - e20); e0q[1] = e20;
    }

    // ---- serial DP: len-1 steps, ONE named barrier each ----
#pragma unroll 4
    for (int t = 0; t < len - 1; t++) {
        int buf = t & 1, nbuf = buf ^ 1, p = t & 3;
        GBAR();

        float inv = sm_inv[gid][buf];
        const ulonglong2* pp = (const ulonglong2*)sm_u[gid][buf];
        unsigned long long acc0 = 0, acc1 = 0, acc2 = 0, acc3 = 0;
#pragma unroll
        for (int q = 0; q < 16; q += 2) {
            ulonglong2 va = pp[q];
            ulonglong2 vb = pp[q + 1];
            FMA2(acc0, va.x, eT2[2*q]);
            FMA2(acc1, va.y, eT2[2*q+1]);
            FMA2(acc2, vb.x, eT2[2*q+2]);
            FMA2(acc3, vb.y, eT2[2*q+3]);
        }
        float s;
        {
            float l0, h0, l1, h1, l2, h2, l3, h3;
            asm("mov.b64 {%0,%1}, %2;" : "=f"(l0), "=f"(h0) : "l"(acc0));
            asm("mov.b64 {%0,%1}, %2;" : "=f"(l1), "=f"(h1) : "l"(acc1));
            asm("mov.b64 {%0,%1}, %2;" : "=f"(l2), "=f"(h2) : "l"(acc2));
            asm("mov.b64 {%0,%1}, %2;" : "=f"(l3), "=f"(h3) : "l"(acc3));
            s = ((l0 + h0) + (l1 + h1)) + ((l2 + h2) + (l3 + h3));
        }
        float un = s * (xq[buf] * inv);
        sm_u[gid][nbuf][j] = un;
        if (j == 0) {
            float invn;
            asm("rcp.approx.f32 %0, %1;" : "=f"(invn) : "f"(s));
            sm_inv[gid][nbuf] = invn;
            C += e0q[buf] - __logf(inv);   // exact: uses ACTUAL inv applied
        }
        u_reg = un;

        // refill exp stage from raw ring (time t+3), reload ring (time t+7)
        float r0 = raw0[p];
        xq[buf] = __expf(rawJ[p] - r0);
        e0q[buf] = r0;
        int tl = (t + 7 < len) ? t + 7 : len - 1;
        size_t base = ((size_t)tl * B_DIM + b) * K_DIM;
        rawJ[p] = g_em[base + j];
        raw0[p] = g_em[base];
    }

    // ---- forward = C + log(sum_j u_j * exp(end_j)) ----
    float val = u_reg * __expf(endt[j]);
#pragma unroll
    for (int o = 16; o; o >>= 1) val += __shfl_down_sync(0xffffffffu, val, o);
    if (lane == 0) sm_g[gid][wing] = val;
    GBAR();
    if (j == 0) {
        float fwd = C + __logf(sm_g[gid][0] + sm_g[gid][1]);
        g_diff[b] = fwd - goldv;
    }
#undef GBAR

    // ---- fused deterministic final reduction (last block) ----
    __syncthreads();
    __shared__ unsigned int s_last;
    if (tid == 0) {
        __threadfence();
        unsigned int old = atomicAdd(&g_cnt, 1u);
        s_last = (old == (unsigned)(gridDim.x - 1)) ? 1u : 0u;
    }
    __syncthreads();
    if (s_last) {
        __shared__ float sr[128];
        if (tid == 0) __threadfence();
        __syncthreads();
        float v = __ldcg(&g_diff[tid]) + __ldcg(&g_diff[tid + 128]);
        sr[tid] = v;
        __syncthreads();
        for (int k = 64; k > 0; k >>= 1) {
            if (tid < k) sr[tid] += sr[tid + k];
            __syncthreads();
        }
        if (tid == 0) {
            out[0] = sr[0];
            g_cnt = 0;   // reset for next graph replay
        }
    }
}

// ---------------------------------------------------------------------------
extern "C" void kernel_launch(void* const* d_in, const int* in_sizes, int n_in,
                              void* d_out, int out_size) {
    const float* hiddens = (const float*)d_in[0];   // [T,B,H] f32
    const int*   lens    = (const int*)d_in[1];     // [B]
    const int*   tags    = (const int*)d_in[2];     // [T,B]
    const float* W       = (const float*)d_in[3];   // [K,H]
    const float* bias    = (const float*)d_in[4];   // [K]
    const float* begin   = (const float*)d_in[5];   // [K]
    const float* trans   = (const float*)d_in[6];   // [K,K]
    const float* endt    = (const float*)d_in[7];   // [K]
    float* out = (float*)d_out;

    cudaFuncSetAttribute(emis_gemm, cudaFuncAttributeMaxDynamicSharedMemorySize, 65536);

    emis_gemm<<<M_DIM / 256, 256, 65536>>>(hiddens, W, bias);
    crf_dp<<<B_DIM / 2, 128>>>(lens, tags, trans, begin, endt, out);
}